// round 4
// baseline (speedup 1.0000x reference)
#include <cuda_runtime.h>
#include <cuda_bf16.h>
#include <math.h>

#define BB 4
#define LL 64
#define DD 64
#define RELN 16
#define NEGV (-1e9f)

// ---------------- fast math helpers ------------------------------------------
__device__ __forceinline__ float rcpa(float x) {
    float y; asm("rcp.approx.f32 %0, %1;" : "=f"(y) : "f"(x)); return y;
}
__device__ __forceinline__ float sigm(float x)  { return rcpa(1.f + __expf(-x)); }
__device__ __forceinline__ float tanha(float x) { return 1.f - 2.f * rcpa(__expf(2.f * x) + 1.f); }

// ---------------- packed f32x2 FMA helpers ------------------------------------
__device__ __forceinline__ void fma2(unsigned long long& d,
                                     unsigned long long a, unsigned long long b) {
    asm("fma.rn.f32x2 %0, %1, %2, %0;" : "+l"(d) : "l"(a), "l"(b));
}
__device__ __forceinline__ void unpack2(unsigned long long v, float& x, float& y) {
    asm("mov.b64 {%0,%1}, %2;" : "=f"(x), "=f"(y) : "l"(v));
}
__device__ __forceinline__ float dot64(const ulonglong2* __restrict__ a,
                                       const ulonglong2* __restrict__ b) {
    unsigned long long a0 = 0ULL, a1 = 0ULL, a2 = 0ULL, a3 = 0ULL;
#pragma unroll
    for (int q = 0; q < 16; q += 2) {
        ulonglong2 x = a[q], y = b[q];
        ulonglong2 x2 = a[q + 1], y2 = b[q + 1];
        fma2(a0, x.x, y.x);  fma2(a1, x.y, y.y);
        fma2(a2, x2.x, y2.x); fma2(a3, x2.y, y2.y);
    }
    float s0, s1, s2, s3, s4, s5, s6, s7;
    unpack2(a0, s0, s1); unpack2(a1, s2, s3);
    unpack2(a2, s4, s5); unpack2(a3, s6, s7);
    return ((s0 + s1) + (s2 + s3)) + ((s4 + s5) + (s6 + s7));
}

// ---------------- global scratch & sync state ---------------------------------
__device__ __align__(16) float g_o[BB * LL * DD];
__device__ __align__(16) float g_v[BB * RELN * LL * DD];
__device__ __align__(16) float g_gx[BB * LL * 3 * DD];
__device__ unsigned long long g_lossint;   // fixed-point loss accumulator (2^42)
__device__ unsigned int g_ka_cnt;          // ka-phase completion counter
__device__ unsigned int g_kb_cnt;          // kb-phase completion counter
__device__ unsigned int g_loss_cnt;        // loss finisher counter
// all four reset to 0 by the elected finisher each launch (zero-initialized at load)

#define LOSS_SCALE 4398046511104.0   // 2^42

// shared-memory phase union (~18.5 KB)
struct PhaseA { float so[LL * DD]; };
struct PhaseB {
    float sob[LL][DD + 1];
    float soi[DD]; float sp[LL]; float sctx[DD]; float so2[DD];
    float wred[4];
};
struct PhaseC {
    float shseq[LL][DD];
    float sh[DD]; float sgh[3 * DD];
    float sga[LL][3]; float sa[LL]; float sw[LL];
    float sc[DD]; float sh1[DD / 2]; float slog[2]; float wred[4];
    int smaxl;
};
union SmemU { PhaseA a; PhaseB b; PhaseC c; };

__global__ void __launch_bounds__(128)
mega(const int* __restrict__ x, const int* __restrict__ yv,
     const int* __restrict__ r, const int* __restrict__ lv,
     const float* __restrict__ emb, const float* __restrict__ rel,
     const float* __restrict__ attW, const float* __restrict__ attb,
     const float* __restrict__ gWih, const float* __restrict__ Whh,
     const float* __restrict__ gbih, const float* __restrict__ bhh,
     const float* __restrict__ oWih, const float* __restrict__ oWhh,
     const float* __restrict__ obih, const float* __restrict__ obhh,
     const float* __restrict__ W1, const float* __restrict__ b1,
     const float* __restrict__ W2, const float* __restrict__ b2,
     float* __restrict__ out, int out_size) {
    __shared__ __align__(16) SmemU smem;
    int blk = blockIdx.x;     // 256 blocks
    int tid = threadIdx.x;    // 128 threads

    // ================= phase 0: relation matvec (blocks 0..127) =============
    if (blk < 128) {
        int b    = blk >> 5;
        int k    = (blk >> 1) & 15;
        int half = blk & 1;
        float* so = smem.a.so;
        for (int i = tid; i < LL * DD; i += 128) {
            int l = i >> 6;
            int d = i & 63;
            so[i] = emb[x[b * LL + l] * DD + d];
        }
        __syncthreads();
        if (k == 0 && half == 0) {
            for (int i = tid; i < LL * DD; i += 128) g_o[b * LL * DD + i] = so[i];
        }
        int d  = tid & 63;
        int jg = tid >> 6;                  // 0..1
        ulonglong2 m[16];
        const ulonglong2* mrow =
            reinterpret_cast<const ulonglong2*>(rel + k * DD * DD + d * DD);
#pragma unroll
        for (int q = 0; q < 16; q++) m[q] = mrow[q];
        int jbase = half * 32 + jg * 16;
#pragma unroll
        for (int jj = 0; jj < 16; jj++) {
            int j = jbase + jj;
            const ulonglong2* orow = reinterpret_cast<const ulonglong2*>(so + j * DD);
            unsigned long long a0 = 0ULL, a1 = 0ULL, a2 = 0ULL, a3 = 0ULL;
#pragma unroll
            for (int q = 0; q < 16; q += 2) {
                ulonglong2 ov = orow[q], ov2 = orow[q + 1];
                fma2(a0, m[q].x, ov.x);      fma2(a1, m[q].y, ov.y);
                fma2(a2, m[q + 1].x, ov2.x); fma2(a3, m[q + 1].y, ov2.y);
            }
            float s0, s1, s2, s3, s4, s5, s6, s7;
            unpack2(a0, s0, s1); unpack2(a1, s2, s3);
            unpack2(a2, s4, s5); unpack2(a3, s6, s7);
            g_v[(((b * RELN + k) * LL + j) * DD) + d] =
                ((s0 + s1) + (s2 + s3)) + ((s4 + s5) + (s6 + s7));
        }
        __syncthreads();
        if (tid == 0) { __threadfence(); atomicAdd(&g_ka_cnt, 1u); }
    }

    // ---- wait: all ka blocks done ----
    if (tid == 0) {
        while (*(volatile unsigned int*)&g_ka_cnt < 128u) __nanosleep(128);
    }
    __syncthreads();
    __threadfence();

    // ================= phase 1: attention column (all 256 blocks) ============
    {
        int b = blk >> 6;
        int i = blk & 63;
        PhaseB& S = smem.b;

        const float* ob = g_o + b * LL * DD;
        for (int idx = tid; idx < LL * DD; idx += 128) {
            S.sob[idx >> 6][idx & 63] = ob[idx];
        }
        __syncthreads();
        if (tid < DD) S.soi[tid] = S.sob[i][tid];
        __syncthreads();

        if (tid < DD) {
            int j = tid;
            int rj = r[(b * LL + i) * LL + j];
            float s;
            if (rj > 0) {
                s = dot64(reinterpret_cast<const ulonglong2*>(
                              g_v + (((b * RELN + rj) * LL + j) * DD)),
                          reinterpret_cast<const ulonglong2*>(S.soi));
            } else {
                s = NEGV;
            }
            float mx = s;
#pragma unroll
            for (int off = 16; off; off >>= 1)
                mx = fmaxf(mx, __shfl_xor_sync(0xFFFFFFFFu, mx, off));
            if ((tid & 31) == 0) S.wred[tid >> 5] = mx;
            S.sp[j] = s;     // stash raw score
        }
        __syncthreads();
        if (tid < DD) {
            float mx = fmaxf(S.wred[0], S.wred[1]);
            float e = __expf(S.sp[tid] - mx);
            float ss = e;
#pragma unroll
            for (int off = 16; off; off >>= 1) ss += __shfl_xor_sync(0xFFFFFFFFu, ss, off);
            if ((tid & 31) == 0) S.wred[2 + (tid >> 5)] = ss;
            S.sp[tid] = e;
        }
        __syncthreads();
        if (tid < DD) {
            float inv = rcpa(S.wred[2] + S.wred[3]);
            float acc = 0.f;
#pragma unroll 8
            for (int jj = 0; jj < LL; jj++) acc += S.sp[jj] * S.sob[jj][tid];
            S.sctx[tid] = acc * inv;
        }
        __syncthreads();
        if (tid < DD) {
            S.so2[tid] = attb[tid] +
                dot64(reinterpret_cast<const ulonglong2*>(attW + tid * DD),
                      reinterpret_cast<const ulonglong2*>(S.sctx));
        }
        __syncthreads();

        float* gxout = g_gx + (b * LL + i) * (3 * DD);
        {
            int g = tid;            // rows 0..127
            gxout[g] = gbih[g] +
                dot64(reinterpret_cast<const ulonglong2*>(gWih + g * DD),
                      reinterpret_cast<const ulonglong2*>(S.so2));
            if (tid < DD) {
                int g2 = 128 + tid; // rows 128..191
                gxout[g2] = gbih[g2] +
                    dot64(reinterpret_cast<const ulonglong2*>(gWih + g2 * DD),
                          reinterpret_cast<const ulonglong2*>(S.so2));
            }
        }
        __syncthreads();
        if (tid == 0) { __threadfence(); atomicAdd(&g_kb_cnt, 1u); }
    }

    if (blk >= BB) return;   // only blocks 0..3 continue

    // ---- wait: all kb blocks done ----
    if (tid == 0) {
        while (*(volatile unsigned int*)&g_kb_cnt < 256u) __nanosleep(128);
    }
    __syncthreads();
    __threadfence();

    // ================= phase 2: GRU + out-GRU + classifier (blocks 0..3) ====
    {
        int b = blk;
        int k = tid;              // 0..127
        PhaseC& C = smem.c;

        // Whh rows: thread k owns row k; threads <64 also own row 128+k
        ulonglong2 w[16], w2[16];
        {
            const ulonglong2* wr = reinterpret_cast<const ulonglong2*>(Whh + k * DD);
#pragma unroll
            for (int q = 0; q < 16; q++) w[q] = wr[q];
            if (k < DD) {
                const ulonglong2* wr2 =
                    reinterpret_cast<const ulonglong2*>(Whh + (128 + k) * DD);
#pragma unroll
                for (int q = 0; q < 16; q++) w2[q] = wr2[q];
            }
        }
        float bk = bhh[k];
        float bk2 = (k < DD) ? bhh[128 + k] : 0.f;

        if (k < DD) C.sh[k] = 0.f;
        if (k == 0) {
            int m = lv[0];
#pragma unroll
            for (int i = 1; i < BB; i++) m = max(m, lv[i]);
            C.smaxl = m + 1;
        }
        __syncthreads();

        const float* gxb = g_gx + b * LL * (3 * DD);
        float xr = 0.f, xz = 0.f, xn = 0.f;
        if (k < DD) { xr = gxb[k]; xz = gxb[DD + k]; xn = gxb[2 * DD + k]; }

        for (int l = 0; l < LL; l++) {
            const ulonglong2* h2 = reinterpret_cast<const ulonglong2*>(C.sh);
            unsigned long long a0 = 0ULL, a1 = 0ULL, a2 = 0ULL, a3 = 0ULL;
#pragma unroll
            for (int q = 0; q < 16; q += 2) {
                ulonglong2 hA = h2[q], hB = h2[q + 1];
                fma2(a0, w[q].x, hA.x);     fma2(a1, w[q].y, hA.y);
                fma2(a2, w[q + 1].x, hB.x); fma2(a3, w[q + 1].y, hB.y);
            }
            float s0, s1, s2, s3, s4, s5, s6, s7;
            unpack2(a0, s0, s1); unpack2(a1, s2, s3);
            unpack2(a2, s4, s5); unpack2(a3, s6, s7);
            C.sgh[k] = bk + ((s0 + s1) + (s2 + s3)) + ((s4 + s5) + (s6 + s7));
            if (k < DD) {
                unsigned long long c0 = 0ULL, c1 = 0ULL, c2 = 0ULL, c3 = 0ULL;
#pragma unroll
                for (int q = 0; q < 16; q += 2) {
                    ulonglong2 hA = h2[q], hB = h2[q + 1];
                    fma2(c0, w2[q].x, hA.x);     fma2(c1, w2[q].y, hA.y);
                    fma2(c2, w2[q + 1].x, hB.x); fma2(c3, w2[q + 1].y, hB.y);
                }
                float t0, t1, t2, t3, t4, t5, t6, t7;
                unpack2(c0, t0, t1); unpack2(c1, t2, t3);
                unpack2(c2, t4, t5); unpack2(c3, t6, t7);
                C.sgh[128 + k] = bk2 + ((t0 + t1) + (t2 + t3)) + ((t4 + t5) + (t6 + t7));
            }
            __syncthreads();
            if (k < DD) {
                float hr = C.sgh[k];
                float hz = C.sgh[DD + k];
                float hn = C.sgh[2 * DD + k];
                float rg = sigm(xr + hr);
                float zg = sigm(xz + hz);
                float ng = tanha(xn + rg * hn);
                float hnew = (1.f - zg) * ng + zg * C.sh[k];
                C.sh[k] = hnew;
                C.shseq[l][k] = hnew;
                if (l + 1 < LL) {
                    const float* nx = gxb + (l + 1) * 3 * DD;
                    xr = nx[k]; xz = nx[DD + k]; xn = nx[2 * DD + k];
                }
            }
            __syncthreads();
        }

        // out-GRU input projections: 192 jobs (l,g)
        {
            int job = k;                    // 0..127
            int l = job & 63, g = job >> 6; // g 0..1
            C.sga[l][g] = obih[g] +
                dot64(reinterpret_cast<const ulonglong2*>(C.shseq[l]),
                      reinterpret_cast<const ulonglong2*>(oWih + g * DD));
            if (k < DD) {                   // jobs 128..191 -> g=2
                C.sga[k][2] = obih[2] +
                    dot64(reinterpret_cast<const ulonglong2*>(C.shseq[k]),
                          reinterpret_cast<const ulonglong2*>(oWih + 2 * DD));
            }
        }
        __syncthreads();

        // scalar GRU recurrence (serial, thread 0)
        if (k == 0) {
            float h = 0.f;
            float w0 = oWhh[0], w1 = oWhh[1], wn = oWhh[2];
            float c0 = obhh[0], c1 = obhh[1], cn = obhh[2];
            for (int l = 0; l < LL; l++) {
                float rg = sigm(C.sga[l][0] + h * w0 + c0);
                float zg = sigm(C.sga[l][1] + h * w1 + c1);
                float ng = tanha(C.sga[l][2] + rg * (h * wn + cn));
                h = (1.f - zg) * ng + zg * h;
                C.sa[l] = h;
            }
        }
        __syncthreads();

        // masked softmax over L (threads 0..63)
        if (k < DD) {
            float v = (k < C.smaxl) ? C.sa[k] : NEGV;
            float mx = v;
#pragma unroll
            for (int off = 16; off; off >>= 1)
                mx = fmaxf(mx, __shfl_xor_sync(0xFFFFFFFFu, mx, off));
            if ((k & 31) == 0) C.wred[k >> 5] = mx;
            C.sa[k] = v;
        }
        __syncthreads();
        if (k < DD) {
            float mx = fmaxf(C.wred[0], C.wred[1]);
            float e = __expf(C.sa[k] - mx);
            float ss = e;
#pragma unroll
            for (int off = 16; off; off >>= 1) ss += __shfl_xor_sync(0xFFFFFFFFu, ss, off);
            if ((k & 31) == 0) C.wred[2 + (k >> 5)] = ss;
            C.sw[k] = e;
        }
        __syncthreads();

        // pooled context
        if (k < DD) {
            float inv = rcpa(C.wred[2] + C.wred[3]);
            float acc = 0.f;
#pragma unroll 8
            for (int l = 0; l < LL; l++) acc += C.sw[l] * C.shseq[l][k];
            C.sc[k] = acc * inv;
        }
        __syncthreads();

        if (k < 32) {
            float acc = b1[k] +
                dot64(reinterpret_cast<const ulonglong2*>(W1 + k * DD),
                      reinterpret_cast<const ulonglong2*>(C.sc));
            C.sh1[k] = fmaxf(acc, 0.f);
        }
        __syncthreads();

        if (k < 2) {
            const float* wr2 = W2 + k * 32;
            float acc = b2[k];
#pragma unroll
            for (int m = 0; m < 32; m++) acc += C.sh1[m] * wr2[m];
            C.slog[k] = acc;
        }
        __syncthreads();

        // y_hat + deterministic loss accumulation + finisher
        if (k == 0) {
            float a0 = C.slog[0], a1 = C.slog[1];
            float mx = fmaxf(a0, a1);
            float e0 = __expf(a0 - mx), e1 = __expf(a1 - mx);
            float z = e0 + e1;
            float invz = rcpa(z);
            if (2 * b < out_size)     out[2 * b]     = e0 * invz;
            if (2 * b + 1 < out_size) out[2 * b + 1] = e1 * invz;
            float chosen = (yv[b] == 0) ? a0 : a1;
            float t = -(chosen - mx - __logf(z));          // > 0
            unsigned long long enc =
                (unsigned long long)((double)t * LOSS_SCALE);
            atomicAdd(&g_lossint, enc);
            __threadfence();
            unsigned int c = atomicAdd(&g_loss_cnt, 1u);
            if (c == 3u) {
                unsigned long long s = atomicAdd(&g_lossint, 0ULL);
                if (out_size > 8)
                    out[8] = (float)((double)s * (1.0 / (4.0 * LOSS_SCALE)));
                for (int i = 9; i < out_size; i++) out[i] = 0.f;
                // reset sync state for next graph replay
                g_loss_cnt = 0u;
                g_ka_cnt = 0u;
                g_kb_cnt = 0u;
                g_lossint = 0ULL;
                __threadfence();
            }
        }
    }
}

// ---------------- launch ------------------------------------------------------
extern "C" void kernel_launch(void* const* d_in, const int* in_sizes, int n_in,
                              void* d_out, int out_size) {
    const int*   x    = (const int*)  d_in[0];
    const int*   y    = (const int*)  d_in[1];
    const int*   r    = (const int*)  d_in[2];
    const int*   l    = (const int*)  d_in[3];
    const float* emb  = (const float*)d_in[4];
    const float* rel  = (const float*)d_in[5];
    const float* attW = (const float*)d_in[6];
    const float* attb = (const float*)d_in[7];
    const float* gWih = (const float*)d_in[8];
    const float* gWhh = (const float*)d_in[9];
    const float* gbih = (const float*)d_in[10];
    const float* gbhh = (const float*)d_in[11];
    const float* oWih = (const float*)d_in[12];
    const float* oWhh = (const float*)d_in[13];
    const float* obih = (const float*)d_in[14];
    const float* obhh = (const float*)d_in[15];
    const float* W1   = (const float*)d_in[16];
    const float* b1   = (const float*)d_in[17];
    const float* W2   = (const float*)d_in[18];
    const float* b2   = (const float*)d_in[19];

    mega<<<256, 128>>>(x, y, r, l, emb, rel, attW, attb,
                       gWih, gWhh, gbih, gbhh,
                       oWih, oWhh, obih, obhh,
                       W1, b1, W2, b2, (float*)d_out, out_size);
}

// round 5
// speedup vs baseline: 1.0303x; 1.0303x over previous
#include <cuda_runtime.h>
#include <cuda_bf16.h>
#include <math.h>

#define BB 4
#define LL 64
#define DD 64
#define RELN 16
#define NEGV (-1e9f)
#define LOSS_SCALE 4398046511104.0   // 2^42

// ---------------- fast math helpers ------------------------------------------
__device__ __forceinline__ float rcpa(float x) {
    float y; asm("rcp.approx.f32 %0, %1;" : "=f"(y) : "f"(x)); return y;
}
__device__ __forceinline__ float sigm(float x)  { return rcpa(1.f + __expf(-x)); }
__device__ __forceinline__ float tanha(float x) { return 1.f - 2.f * rcpa(__expf(2.f * x) + 1.f); }

// ---------------- packed f32x2 FMA helpers ------------------------------------
__device__ __forceinline__ void fma2(unsigned long long& d,
                                     unsigned long long a, unsigned long long b) {
    asm("fma.rn.f32x2 %0, %1, %2, %0;" : "+l"(d) : "l"(a), "l"(b));
}
__device__ __forceinline__ void unpack2(unsigned long long v, float& x, float& y) {
    asm("mov.b64 {%0,%1}, %2;" : "=f"(x), "=f"(y) : "l"(v));
}
__device__ __forceinline__ float dot64(const ulonglong2* __restrict__ a,
                                       const ulonglong2* __restrict__ b) {
    unsigned long long a0 = 0ULL, a1 = 0ULL, a2 = 0ULL, a3 = 0ULL;
#pragma unroll
    for (int q = 0; q < 16; q += 2) {
        ulonglong2 x = a[q], y = b[q];
        ulonglong2 x2 = a[q + 1], y2 = b[q + 1];
        fma2(a0, x.x, y.x);  fma2(a1, x.y, y.y);
        fma2(a2, x2.x, y2.x); fma2(a3, x2.y, y2.y);
    }
    float s0, s1, s2, s3, s4, s5, s6, s7;
    unpack2(a0, s0, s1); unpack2(a1, s2, s3);
    unpack2(a2, s4, s5); unpack2(a3, s6, s7);
    return ((s0 + s1) + (s2 + s3)) + ((s4 + s5) + (s6 + s7));
}

// ---------------- global scratch & sync ---------------------------------------
__device__ __align__(16) float g_o[BB * LL * DD];
__device__ __align__(16) float g_s[BB * RELN * LL * LL];   // per-relation score maps
__device__ __align__(16) float g_gx[BB * LL * 3 * DD];
__device__ unsigned long long g_lossint;
__device__ unsigned int g_pA, g_pB, g_loss;   // zero-init; finisher resets each launch

struct PA { float so[LL * DD]; float sv[16 * DD]; };
struct PB { float sob[LL][DD + 1]; float sp[LL]; float sctx[DD]; float so2[DD]; float wred[4]; };
struct PC {
    float shseq[LL][DD];
    float sga[LL][3]; float sa[LL]; float sw[LL];
    float sc[DD]; float sh1[DD / 2]; float slog[2]; float wred[4];
    int smaxl;
};
union SmemU { PA a; PB b; PC c; };

__global__ void __launch_bounds__(128)
mega(const int* __restrict__ x, const int* __restrict__ yv,
     const int* __restrict__ r, const int* __restrict__ lv,
     const float* __restrict__ emb, const float* __restrict__ rel,
     const float* __restrict__ attW, const float* __restrict__ attb,
     const float* __restrict__ gWih, const float* __restrict__ Whh,
     const float* __restrict__ gbih, const float* __restrict__ bhh,
     const float* __restrict__ oWih, const float* __restrict__ oWhh,
     const float* __restrict__ obih, const float* __restrict__ obhh,
     const float* __restrict__ W1, const float* __restrict__ b1,
     const float* __restrict__ W2, const float* __restrict__ b2,
     float* __restrict__ out, int out_size) {
    __shared__ __align__(16) SmemU smem;
    int blk = blockIdx.x;     // 256
    int tid = threadIdx.x;    // 128

    // ========== Phase A: S_k score maps. blk -> (b, k, quarter) =============
    {
        int b = blk >> 6;
        int k = (blk >> 2) & 15;
        int q4 = blk & 3;                  // j-quarter
        float* so = smem.a.so;
        float* sv = smem.a.sv;             // [16][64] v rows for this quarter

        for (int idx = tid; idx < LL * DD; idx += 128) {
            int l = idx >> 6, d = idx & 63;
            so[idx] = emb[x[b * LL + l] * DD + d];
        }
        __syncthreads();
        if (k == 0 && q4 == 0) {
            for (int idx = tid; idx < LL * DD; idx += 128) g_o[b * LL * DD + idx] = so[idx];
        }

        int d    = tid & 63;
        int jgrp = tid >> 6;               // 0..1
        // V-part: v[jl][d] = M_k[d,:] . o[j,:]
        ulonglong2 m[16];
        const ulonglong2* mrow = reinterpret_cast<const ulonglong2*>(rel + (k * DD + d) * DD);
#pragma unroll
        for (int qq = 0; qq < 16; qq++) m[qq] = mrow[qq];
#pragma unroll
        for (int jj = 0; jj < 8; jj++) {
            int jl = jgrp * 8 + jj;
            int j  = q4 * 16 + jl;
            float v = dot64(m, reinterpret_cast<const ulonglong2*>(so + j * DD));
            sv[jl * DD + d] = v;
        }
        __syncthreads();
        // S-part: S[i][j] = o[i,:] . v[jl,:]
        int i = tid & 63;
        ulonglong2 oi[16];
        const ulonglong2* oir = reinterpret_cast<const ulonglong2*>(so + i * DD);
#pragma unroll
        for (int qq = 0; qq < 16; qq++) oi[qq] = oir[qq];
        float res[8];
#pragma unroll
        for (int jj = 0; jj < 8; jj++) {
            int jl = jgrp * 8 + jj;
            res[jj] = dot64(oi, reinterpret_cast<const ulonglong2*>(sv + jl * DD));
        }
        float4* dst = reinterpret_cast<float4*>(
            g_s + (((b * RELN + k) * LL + i) * LL) + q4 * 16 + jgrp * 8);
        dst[0] = make_float4(res[0], res[1], res[2], res[3]);
        dst[1] = make_float4(res[4], res[5], res[6], res[7]);
        __syncthreads();
        if (tid == 0) { __threadfence(); atomicAdd(&g_pA, 1u); }
    }

    if (tid == 0) { while (*(volatile unsigned int*)&g_pA < 256u) __nanosleep(64); }
    __syncthreads();
    __threadfence();

    // ========== Phase B: softmax + context + projections. blk -> (b, i) =====
    {
        int b = blk >> 6;
        int i = blk & 63;
        PB& S = smem.b;

        const float* ob = g_o + b * LL * DD;
        for (int idx = tid; idx < LL * DD; idx += 128)
            S.sob[idx >> 6][idx & 63] = ob[idx];
        __syncthreads();

        if (tid < DD) {
            int j = tid;
            int rj = r[(b * LL + i) * LL + j];
            float s = (rj > 0) ? g_s[(((b * RELN + rj) * LL + i) * LL) + j] : NEGV;
            float mx = s;
#pragma unroll
            for (int off = 16; off; off >>= 1)
                mx = fmaxf(mx, __shfl_xor_sync(0xFFFFFFFFu, mx, off));
            if ((tid & 31) == 0) S.wred[tid >> 5] = mx;
            S.sp[j] = s;
        }
        __syncthreads();
        if (tid < DD) {
            float mx = fmaxf(S.wred[0], S.wred[1]);
            float e = __expf(S.sp[tid] - mx);
            float ss = e;
#pragma unroll
            for (int off = 16; off; off >>= 1) ss += __shfl_xor_sync(0xFFFFFFFFu, ss, off);
            if ((tid & 31) == 0) S.wred[2 + (tid >> 5)] = ss;
            S.sp[tid] = e;
        }
        __syncthreads();
        if (tid < DD) {
            float inv = rcpa(S.wred[2] + S.wred[3]);
            float acc = 0.f;
#pragma unroll 8
            for (int jj = 0; jj < LL; jj++) acc += S.sp[jj] * S.sob[jj][tid];
            S.sctx[tid] = acc * inv;
        }
        __syncthreads();
        if (tid < DD) {
            S.so2[tid] = attb[tid] +
                dot64(reinterpret_cast<const ulonglong2*>(attW + tid * DD),
                      reinterpret_cast<const ulonglong2*>(S.sctx));
        }
        __syncthreads();
        float* gxout = g_gx + (b * LL + i) * (3 * DD);
        gxout[tid] = gbih[tid] +
            dot64(reinterpret_cast<const ulonglong2*>(gWih + tid * DD),
                  reinterpret_cast<const ulonglong2*>(S.so2));
        if (tid < DD) {
            int g2 = 128 + tid;
            gxout[g2] = gbih[g2] +
                dot64(reinterpret_cast<const ulonglong2*>(gWih + g2 * DD),
                      reinterpret_cast<const ulonglong2*>(S.so2));
        }
        __syncthreads();
        if (tid == 0) { __threadfence(); atomicAdd(&g_pB, 1u); }
    }

    if (blk >= BB) return;

    if (tid == 0) { while (*(volatile unsigned int*)&g_pB < 256u) __nanosleep(64); }
    __syncthreads();
    __threadfence();

    // ========== Phase C: GRU + out-GRU + classifier. blocks 0..3 ============
    {
        int b = blk;
        int k = tid;
        PC& C = smem.c;

        // thread k (<64) owns all three gate rows of Whh
        ulonglong2 wR[16], wZ[16], wN[16];
        float bR = 0.f, bZ = 0.f, bN = 0.f;
        if (k < DD) {
            const ulonglong2* p0 = reinterpret_cast<const ulonglong2*>(Whh + k * DD);
            const ulonglong2* p1 = reinterpret_cast<const ulonglong2*>(Whh + (DD + k) * DD);
            const ulonglong2* p2 = reinterpret_cast<const ulonglong2*>(Whh + (2 * DD + k) * DD);
#pragma unroll
            for (int qq = 0; qq < 16; qq++) { wR[qq] = p0[qq]; wZ[qq] = p1[qq]; wN[qq] = p2[qq]; }
            bR = bhh[k]; bZ = bhh[DD + k]; bN = bhh[2 * DD + k];
        }
        if (k == 0) {
            int m = lv[0];
#pragma unroll
            for (int i = 1; i < BB; i++) m = max(m, lv[i]);
            C.smaxl = m + 1;
        }

        const float* gxb = g_gx + b * LL * (3 * DD);
        float xr = 0.f, xz = 0.f, xn = 0.f, hown = 0.f;
        if (k < DD) { xr = gxb[k]; xz = gxb[DD + k]; xn = gxb[2 * DD + k]; }

        // ---- step 0: h=0 -> gh = bhh ----
        if (k < DD) {
            float rg = sigm(xr + bR);
            float zg = sigm(xz + bZ);
            float ng = tanha(xn + rg * bN);
            hown = (1.f - zg) * ng;
            C.shseq[0][k] = hown;
            const float* nx = gxb + 3 * DD;
            xr = nx[k]; xz = nx[DD + k]; xn = nx[2 * DD + k];
        }
        __syncthreads();

        // ---- steps 1..63: read h from shseq[l-1], one barrier per step ----
        for (int l = 1; l < LL; l++) {
            if (k < DD) {
                ulonglong2 h2[16];
                const ulonglong2* hp = reinterpret_cast<const ulonglong2*>(C.shseq[l - 1]);
#pragma unroll
                for (int qq = 0; qq < 16; qq++) h2[qq] = hp[qq];
                unsigned long long aR0 = 0ULL, aR1 = 0ULL, aZ0 = 0ULL, aZ1 = 0ULL,
                                   aN0 = 0ULL, aN1 = 0ULL;
#pragma unroll
                for (int qq = 0; qq < 16; qq++) {
                    fma2(aR0, wR[qq].x, h2[qq].x); fma2(aR1, wR[qq].y, h2[qq].y);
                    fma2(aZ0, wZ[qq].x, h2[qq].x); fma2(aZ1, wZ[qq].y, h2[qq].y);
                    fma2(aN0, wN[qq].x, h2[qq].x); fma2(aN1, wN[qq].y, h2[qq].y);
                }
                float r0, r1, r2, r3, z0, z1, z2, z3, n0, n1, n2, n3;
                unpack2(aR0, r0, r1); unpack2(aR1, r2, r3);
                unpack2(aZ0, z0, z1); unpack2(aZ1, z2, z3);
                unpack2(aN0, n0, n1); unpack2(aN1, n2, n3);
                float hr = bR + (r0 + r1) + (r2 + r3);
                float hz = bZ + (z0 + z1) + (z2 + z3);
                float hn = bN + (n0 + n1) + (n2 + n3);
                float rg = sigm(xr + hr);
                float zg = sigm(xz + hz);
                float ng = tanha(xn + rg * hn);
                hown = (1.f - zg) * ng + zg * hown;
                C.shseq[l][k] = hown;
                if (l + 1 < LL) {
                    const float* nx = gxb + (l + 1) * 3 * DD;
                    xr = nx[k]; xz = nx[DD + k]; xn = nx[2 * DD + k];
                }
            }
            __syncthreads();
        }

        // ---- out-GRU input projections: 192 dots over 128 threads ----
        {
            int l = k & 63, g = k >> 6;    // g 0..1
            C.sga[l][g] = obih[g] +
                dot64(reinterpret_cast<const ulonglong2*>(C.shseq[l]),
                      reinterpret_cast<const ulonglong2*>(oWih + g * DD));
            if (k < DD) {
                C.sga[k][2] = obih[2] +
                    dot64(reinterpret_cast<const ulonglong2*>(C.shseq[k]),
                          reinterpret_cast<const ulonglong2*>(oWih + 2 * DD));
            }
        }
        __syncthreads();

        if (k == 0) {
            float h = 0.f;
            float w0 = oWhh[0], w1 = oWhh[1], wn = oWhh[2];
            float c0 = obhh[0], c1 = obhh[1], cn = obhh[2];
            for (int l = 0; l < LL; l++) {
                float rg = sigm(C.sga[l][0] + h * w0 + c0);
                float zg = sigm(C.sga[l][1] + h * w1 + c1);
                float ng = tanha(C.sga[l][2] + rg * (h * wn + cn));
                h = (1.f - zg) * ng + zg * h;
                C.sa[l] = h;
            }
        }
        __syncthreads();

        if (k < DD) {
            float v = (k < C.smaxl) ? C.sa[k] : NEGV;
            float mx = v;
#pragma unroll
            for (int off = 16; off; off >>= 1)
                mx = fmaxf(mx, __shfl_xor_sync(0xFFFFFFFFu, mx, off));
            if ((k & 31) == 0) C.wred[k >> 5] = mx;
            C.sa[k] = v;
        }
        __syncthreads();
        if (k < DD) {
            float mx = fmaxf(C.wred[0], C.wred[1]);
            float e = __expf(C.sa[k] - mx);
            float ss = e;
#pragma unroll
            for (int off = 16; off; off >>= 1) ss += __shfl_xor_sync(0xFFFFFFFFu, ss, off);
            if ((k & 31) == 0) C.wred[2 + (k >> 5)] = ss;
            C.sw[k] = e;
        }
        __syncthreads();
        if (k < DD) {
            float inv = rcpa(C.wred[2] + C.wred[3]);
            float acc = 0.f;
#pragma unroll 8
            for (int l = 0; l < LL; l++) acc += C.sw[l] * C.shseq[l][k];
            C.sc[k] = acc * inv;
        }
        __syncthreads();
        if (k < 32) {
            float acc = b1[k] +
                dot64(reinterpret_cast<const ulonglong2*>(W1 + k * DD),
                      reinterpret_cast<const ulonglong2*>(C.sc));
            C.sh1[k] = fmaxf(acc, 0.f);
        }
        __syncthreads();
        if (k < 2) {
            const float* wr2 = W2 + k * 32;
            float acc = b2[k];
#pragma unroll
            for (int m = 0; m < 32; m++) acc += C.sh1[m] * wr2[m];
            C.slog[k] = acc;
        }
        __syncthreads();

        if (k == 0) {
            float a0 = C.slog[0], a1 = C.slog[1];
            float mx = fmaxf(a0, a1);
            float e0 = __expf(a0 - mx), e1 = __expf(a1 - mx);
            float z = e0 + e1;
            float invz = rcpa(z);
            if (2 * b < out_size)     out[2 * b]     = e0 * invz;
            if (2 * b + 1 < out_size) out[2 * b + 1] = e1 * invz;
            float chosen = (yv[b] == 0) ? a0 : a1;
            float t = -(chosen - mx - __logf(z));
            atomicAdd(&g_lossint, (unsigned long long)((double)t * LOSS_SCALE));
            __threadfence();
            unsigned int c = atomicAdd(&g_loss, 1u);
            if (c == 3u) {
                unsigned long long s = atomicAdd(&g_lossint, 0ULL);
                if (out_size > 8)
                    out[8] = (float)((double)s * (1.0 / (4.0 * LOSS_SCALE)));
                for (int i = 9; i < out_size; i++) out[i] = 0.f;
                g_loss = 0u; g_pA = 0u; g_pB = 0u; g_lossint = 0ULL;
                __threadfence();
            }
        }
    }
}

// ---------------- launch ------------------------------------------------------
extern "C" void kernel_launch(void* const* d_in, const int* in_sizes, int n_in,
                              void* d_out, int out_size) {
    const int*   x    = (const int*)  d_in[0];
    const int*   y    = (const int*)  d_in[1];
    const int*   r    = (const int*)  d_in[2];
    const int*   l    = (const int*)  d_in[3];
    const float* emb  = (const float*)d_in[4];
    const float* rel  = (const float*)d_in[5];
    const float* attW = (const float*)d_in[6];
    const float* attb = (const float*)d_in[7];
    const float* gWih = (const float*)d_in[8];
    const float* gWhh = (const float*)d_in[9];
    const float* gbih = (const float*)d_in[10];
    const float* gbhh = (const float*)d_in[11];
    const float* oWih = (const float*)d_in[12];
    const float* oWhh = (const float*)d_in[13];
    const float* obih = (const float*)d_in[14];
    const float* obhh = (const float*)d_in[15];
    const float* W1   = (const float*)d_in[16];
    const float* b1   = (const float*)d_in[17];
    const float* W2   = (const float*)d_in[18];
    const float* b2   = (const float*)d_in[19];

    mega<<<256, 128>>>(x, y, r, l, emb, rel, attW, attb,
                       gWih, gWhh, gbih, gbhh,
                       oWih, oWhh, obih, obhh,
                       W1, b1, W2, b2, (float*)d_out, out_size);
}